// round 15
// baseline (speedup 1.0000x reference)
#include <cuda_runtime.h>
#include <cuda_bf16.h>
#include <math.h>
#include <stdint.h>

#define B_   32
#define T_   1024
#define IN_  64
#define RES_ 2048
#define HID_ 512
#define OUT_ 64
#define BT_  (B_ * T_)
#define NCTA_ 128

typedef unsigned long long ull;

// ---- fp32x2 (readout gemm) ----
__device__ __forceinline__ void ffma2(ull& d, ull a, ull b)
{ asm("fma.rn.f32x2 %0, %1, %2, %0;" : "+l"(d) : "l"(a), "l"(b)); }
__device__ __forceinline__ ull splat2(float h)
{ ull r; asm("mov.b64 %0, {%1, %1};" : "=l"(r) : "f"(h)); return r; }
__device__ __forceinline__ void unpack2(ull v, float& lo, float& hi)
{ asm("mov.b64 {%0, %1}, %2;" : "=f"(lo), "=f"(hi) : "l"(v)); }

// ---- acq/rel flags ----
__device__ __forceinline__ unsigned ld_acq(const unsigned* p)
{ unsigned v; asm volatile("ld.acquire.gpu.global.u32 %0, [%1];" : "=r"(v) : "l"(p)); return v; }
__device__ __forceinline__ void st_rel(unsigned* p, unsigned v)
{ asm volatile("st.release.gpu.global.u32 [%0], %1;" :: "l"(p), "r"(v) : "memory"); }

// ---- cp.async ----
__device__ __forceinline__ void cp16(uint32_t saddr, const void* g)
{ asm volatile("cp.async.cg.shared.global [%0], [%1], 16;" :: "r"(saddr), "l"(g) : "memory"); }
#define CP_COMMIT() asm volatile("cp.async.commit_group;" ::: "memory")
template <int N> __device__ __forceinline__ void cp_wait()
{ asm volatile("cp.async.wait_group %0;" :: "n"(N) : "memory"); }

// ---- warp mma bf16 m16n8k16 (validated R10/R12/R13) ----
__device__ __forceinline__ void mma16816(float c[4], const uint32_t a[4], const uint32_t b[2])
{
    asm volatile(
        "mma.sync.aligned.m16n8k16.row.col.f32.bf16.bf16.f32 "
        "{%0,%1,%2,%3},{%4,%5,%6,%7},{%8,%9},{%0,%1,%2,%3};"
        : "+f"(c[0]), "+f"(c[1]), "+f"(c[2]), "+f"(c[3])
        : "r"(a[0]), "r"(a[1]), "r"(a[2]), "r"(a[3]), "r"(b[0]), "r"(b[1]));
}

// ---- scratch ----
__device__ float          g_UT[(size_t)T_ * RES_ * B_];
__device__ __nv_bfloat16  g_hi[2ull * B_ * RES_];   // h hi, [buf][b][k]
__device__ __nv_bfloat16  g_lo[2ull * B_ * RES_];   // h lo residual
__device__ unsigned       g_sf[1024];               // flag[cta] @ cta*8
__device__ float          g_a1[(size_t)BT_ * HID_];
__device__ float          g_a2[(size_t)BT_ * HID_];

// ---------------- U = x @ W_in^T -> UT[t][r][b] ----------------
__global__ void __launch_bounds__(256) u_kernel(const float* __restrict__ x,
                                                const float* __restrict__ Win,
                                                float* __restrict__ UT)
{
    __shared__ float xS[IN_][B_];
    __shared__ float wS[IN_][128];
    const int t = blockIdx.y, R0 = blockIdx.x * 128, tid = threadIdx.x;
    {
        int b = tid >> 3, iq = (tid & 7) * 8;
        const float* src = x + (size_t)b * (T_ * IN_) + (size_t)t * IN_ + iq;
        float4 v0 = *(const float4*)src, v1 = *(const float4*)(src + 4);
        xS[iq+0][b]=v0.x; xS[iq+1][b]=v0.y; xS[iq+2][b]=v0.z; xS[iq+3][b]=v0.w;
        xS[iq+4][b]=v1.x; xS[iq+5][b]=v1.y; xS[iq+6][b]=v1.z; xS[iq+7][b]=v1.w;
    }
    {
        int r = tid >> 1, ih = (tid & 1) * 32;
        const float* src = Win + (size_t)(R0 + r) * IN_ + ih;
#pragma unroll
        for (int j = 0; j < 32; j += 4) {
            float4 v = *(const float4*)(src + j);
            wS[ih+j+0][r]=v.x; wS[ih+j+1][r]=v.y; wS[ih+j+2][r]=v.z; wS[ih+j+3][r]=v.w;
        }
    }
    __syncthreads();
    const int tx = tid & 7, ty = tid >> 3, b0 = tx * 4, r0 = ty * 4;
    float acc[4][4];
#pragma unroll
    for (int i = 0; i < 4; i++)
#pragma unroll
        for (int j = 0; j < 4; j++) acc[i][j] = 0.f;
#pragma unroll
    for (int i = 0; i < IN_; i++) {
        float4 xv = *(const float4*)&xS[i][b0];
        float4 wv = *(const float4*)&wS[i][r0];
        float xa[4] = {xv.x, xv.y, xv.z, xv.w}, wa[4] = {wv.x, wv.y, wv.z, wv.w};
#pragma unroll
        for (int ri = 0; ri < 4; ri++)
#pragma unroll
            for (int bi = 0; bi < 4; bi++) acc[ri][bi] = fmaf(wa[ri], xa[bi], acc[ri][bi]);
    }
    float* dst = UT + (size_t)t * (RES_ * B_);
#pragma unroll
    for (int ri = 0; ri < 4; ri++)
        *(float4*)(dst + (size_t)(R0 + r0 + ri) * B_ + b0) =
            make_float4(acc[ri][0], acc[ri][1], acc[ri][2], acc[ri][3]);
}

// ---------------- warp-MMA persistent scan, R13 chunk pipeline + safe tweaks --------
#define WROWB 4112
#define W_HI  0
#define W_LO  65792
#define BB    131584
#define BBSTR 17408
#define BROW  272
#define REDO  201216
#define SCAN_SMEM 205824

__global__ void __launch_bounds__(256) scan_mma_kernel(const float* __restrict__ Wh,
                                                       float* __restrict__ UT)
{
    extern __shared__ unsigned char smem_raw[];
    unsigned char* sw_hi = smem_raw + W_HI;
    unsigned char* sw_lo = smem_raw + W_LO;
    float* red = (float*)(smem_raw + REDO);
    const uint32_t sbase = (uint32_t)__cvta_generic_to_shared(smem_raw);

    const int tid  = threadIdx.x;
    const int w    = tid >> 5, lane = tid & 31;
    const int g    = lane >> 2, tq = lane & 3;
    const int nt   = w & 3;
    const int kh   = w >> 2;
    const int bid  = blockIdx.x;
    const int R0   = bid * 16;

    // one-time: W rows -> SMEM bf16 hi/lo
    for (int r = 0; r < 16; r++) {
        const float* wrow = Wh + (size_t)(R0 + r) * RES_ + tid * 8;
#pragma unroll
        for (int j = 0; j < 4; j++) {
            float2 v = *(const float2*)(wrow + j * 2);
            __nv_bfloat16 h0 = __float2bfloat16(v.x), h1 = __float2bfloat16(v.y);
            __nv_bfloat16 l0 = __float2bfloat16(v.x - __bfloat162float(h0));
            __nv_bfloat16 l1 = __float2bfloat16(v.y - __bfloat162float(h1));
            unsigned hp = (unsigned)__bfloat16_as_ushort(h0) | ((unsigned)__bfloat16_as_ushort(h1) << 16);
            unsigned lp = (unsigned)__bfloat16_as_ushort(l0) | ((unsigned)__bfloat16_as_ushort(l1) << 16);
            int kbyte = (tid * 8 + j * 2) * 2;
            *(uint32_t*)(sw_hi + r * WROWB + kbyte) = hp;
            *(uint32_t*)(sw_lo + r * WROWB + kbyte) = lp;
        }
    }
    __syncthreads();

    const int ecol = tid & 31;
    const int erow = (tid >> 5) * 2;
    float hprev[2] = {0.f, 0.f};

    const int sr0 = (tid * 2) >> 4,     sg0 = (tid * 2) & 15;
    const int sr1 = (tid * 2 + 1) >> 4, sg1 = (tid * 2 + 1) & 15;

    for (int t = 0; t < T_; t++) {
        const int pr = t & 1;
        const int pw = pr ^ 1;
        const __nv_bfloat16* ghi = g_hi + (size_t)pr * (B_ * RES_);
        const __nv_bfloat16* glo = g_lo + (size_t)pr * (B_ * RES_);
        float* utr = UT + (size_t)t * (RES_ * B_);

        // ---- ONE wait site: bounded raw spin, nanosleep fallback ----
        if (tid < NCTA_) {
            const unsigned* fp = g_sf + tid * 8;
            int it = 0;
            while ((int)(ld_acq(fp) - (unsigned)t) < 0) {
                if (++it > 256) __nanosleep(64);
            }
        }
        __syncthreads();

        // ---- U prefetch: DRAM latency hidden under the whole MMA phase ----
        float u0 = __ldcg(utr + (size_t)(R0 + erow) * B_ + ecol);
        float u1 = __ldcg(utr + (size_t)(R0 + erow + 1) * B_ + ecol);

        // ---- stage: chunk ck -> buf ck&3 (R13-proven liveness) ----
        auto stage = [&](int ck) {
            uint32_t bh = sbase + BB + (uint32_t)(ck & 3) * BBSTR;
            uint32_t bl = bh + 8704;
            cp16(bh + sr0 * BROW + sg0 * 16, ghi + (size_t)sr0 * RES_ + ck * 128 + sg0 * 8);
            cp16(bl + sr0 * BROW + sg0 * 16, glo + (size_t)sr0 * RES_ + ck * 128 + sg0 * 8);
            cp16(bh + sr1 * BROW + sg1 * 16, ghi + (size_t)sr1 * RES_ + ck * 128 + sg1 * 8);
            cp16(bl + sr1 * BROW + sg1 * 16, glo + (size_t)sr1 * RES_ + ck * 128 + sg1 * 8);
            CP_COMMIT();
        };

        float c[4] = {0.f, 0.f, 0.f, 0.f};
        stage(0); stage(1); stage(2);

        for (int ck = 0; ck < 16; ck++) {
            if (ck <= 13) cp_wait<2>(); else if (ck == 14) cp_wait<1>(); else cp_wait<0>();
            __syncthreads();                       // chunk ck resident; buf (ck-1)&3 freed
            if (ck + 3 < 16) stage(ck + 3);        // refill into buf (ck+3)&3 = (ck-1)&3

            const unsigned char* bh = smem_raw + BB + (ck & 3) * BBSTR;
            const unsigned char* bl = bh + 8704;
#pragma unroll
            for (int i = 0; i < 4; i++) {
                int kk = kh * 4 + i;
                unsigned abase = (unsigned)g * WROWB + (unsigned)ck * 256 + kk * 32 + tq * 4;
                uint32_t ah[4], al[4], bhf[2], blf[2];
                ah[0] = *(const uint32_t*)(sw_hi + abase);
                ah[1] = *(const uint32_t*)(sw_hi + abase + 8 * WROWB);
                ah[2] = *(const uint32_t*)(sw_hi + abase + 16);
                ah[3] = *(const uint32_t*)(sw_hi + abase + 8 * WROWB + 16);
                al[0] = *(const uint32_t*)(sw_lo + abase);
                al[1] = *(const uint32_t*)(sw_lo + abase + 8 * WROWB);
                al[2] = *(const uint32_t*)(sw_lo + abase + 16);
                al[3] = *(const uint32_t*)(sw_lo + abase + 8 * WROWB + 16);
                unsigned bbase = (unsigned)(nt * 8 + g) * BROW + kk * 32 + tq * 4;
                bhf[0] = *(const uint32_t*)(bh + bbase);
                bhf[1] = *(const uint32_t*)(bh + bbase + 16);
                blf[0] = *(const uint32_t*)(bl + bbase);
                blf[1] = *(const uint32_t*)(bl + bbase + 16);
                mma16816(c, ah, bhf);
                mma16816(c, ah, blf);
                mma16816(c, al, bhf);
            }
        }

        // ---- frag dump ----
        __syncthreads();
#pragma unroll
        for (int i = 0; i < 4; i++) {
            int row = g + (i >> 1) * 8;
            int col = nt * 8 + tq * 2 + (i & 1);
            red[kh * 576 + row * 36 + col] = c[i];
        }
        __syncthreads();

        // ---- epilogue: tanh -> publish gh -> bar -> flag; UT store AFTER release ----
        float hn0, hn1;
        {
            __nv_bfloat16* whi = g_hi + (size_t)pw * (B_ * RES_);
            __nv_bfloat16* wlo = g_lo + (size_t)pw * (B_ * RES_);
            float s0 = red[erow * 36 + ecol] + red[576 + erow * 36 + ecol];
            float s1 = red[(erow + 1) * 36 + ecol] + red[576 + (erow + 1) * 36 + ecol];
            hn0 = 0.5f * hprev[0] + 0.5f * tanhf(s0 + u0);
            hn1 = 0.5f * hprev[1] + 0.5f * tanhf(s1 + u1);
            hprev[0] = hn0; hprev[1] = hn1;
            __nv_bfloat16 h0 = __float2bfloat16(hn0), h1 = __float2bfloat16(hn1);
            __nv_bfloat16 l0 = __float2bfloat16(hn0 - __bfloat162float(h0));
            __nv_bfloat16 l1 = __float2bfloat16(hn1 - __bfloat162float(h1));
            unsigned hv = (unsigned)__bfloat16_as_ushort(h0) | ((unsigned)__bfloat16_as_ushort(h1) << 16);
            unsigned lv = (unsigned)__bfloat16_as_ushort(l0) | ((unsigned)__bfloat16_as_ushort(l1) << 16);
            size_t koff = (size_t)ecol * RES_ + R0 + erow;
            __stcg((unsigned*)(whi + koff), hv);
            __stcg((unsigned*)(wlo + koff), lv);
        }
        __syncthreads();
        if (tid == 0) st_rel(g_sf + bid * 8, (unsigned)(t + 1));

        // UT (hs) store: off the inter-CTA critical path
        utr[(size_t)(R0 + erow) * B_ + ecol]     = hn0;
        utr[(size_t)(R0 + erow + 1) * B_ + ecol] = hn1;
    }
}

// ---------------- readout gemm (R7 double-buffered, fp32x2) ----------------
__device__ __forceinline__ float gelu_f(float v)
{ return 0.5f * v * (1.0f + erff(v * 0.70710678118654752f)); }

template <int A_MODE, int ACT, int OUT_MODE>
__global__ void __launch_bounds__(256) gemm_kernel(const float* __restrict__ A, int K,
                                                   const float* __restrict__ W,
                                                   const float* __restrict__ bias,
                                                   float* __restrict__ C, int ldc)
{
    __shared__ float As[2][16][132];
    __shared__ float Ws[2][16][64];
    const int m0 = blockIdx.x * 128, n0 = blockIdx.y * 64, tid = threadIdx.x;
    const int tx = tid & 15, ty = tid >> 4;

    int la_b = 0, la_kk = 0, la_tt = 0, la_mm = 0;
    if (A_MODE == 0) {
        int base = tid * 8;
        la_b = base & 31; la_kk = (base >> 5) & 15; la_tt = base >> 9;
        la_mm = la_tt * 32 + la_b;
    } else { la_mm = tid >> 1; la_kk = (tid & 1) * 8; }
    const int lw_n = tid >> 2, lw_kq = (tid & 3) * 4;
    float a_ld[8], w_ld[4];

    auto ldg_tile = [&](int k0) {
        const float* src = (A_MODE == 0)
            ? A + ((size_t)(m0 >> 5) + la_tt) * (RES_ * B_) + (size_t)(k0 + la_kk) * B_ + la_b
            : A + (size_t)(m0 + la_mm) * K + k0 + la_kk;
        float4 v0 = *(const float4*)src, v1 = *(const float4*)(src + 4);
        a_ld[0]=v0.x; a_ld[1]=v0.y; a_ld[2]=v0.z; a_ld[3]=v0.w;
        a_ld[4]=v1.x; a_ld[5]=v1.y; a_ld[6]=v1.z; a_ld[7]=v1.w;
        float4 v = *(const float4*)(W + (size_t)(n0 + lw_n) * K + k0 + lw_kq);
        w_ld[0]=v.x; w_ld[1]=v.y; w_ld[2]=v.z; w_ld[3]=v.w;
    };
    auto sts_tile = [&](int buf) {
        if (A_MODE == 0) {
            *(float4*)&As[buf][la_kk][la_mm]     = make_float4(a_ld[0], a_ld[1], a_ld[2], a_ld[3]);
            *(float4*)&As[buf][la_kk][la_mm + 4] = make_float4(a_ld[4], a_ld[5], a_ld[6], a_ld[7]);
        } else {
#pragma unroll
            for (int j = 0; j < 8; j++) As[buf][la_kk + j][la_mm] = a_ld[j];
        }
#pragma unroll
        for (int j = 0; j < 4; j++) Ws[buf][lw_kq + j][lw_n] = w_ld[j];
    };

    ull c2[4][4];
#pragma unroll
    for (int i = 0; i < 4; i++)
#pragma unroll
        for (int j = 0; j < 4; j++) c2[i][j] = 0ull;

    ldg_tile(0); sts_tile(0); __syncthreads();

    for (int k0 = 0; k0 < K; k0 += 16) {
        const int cur = (k0 >> 4) & 1;
        const bool more = (k0 + 16 < K);
        if (more) ldg_tile(k0 + 16);
#pragma unroll
        for (int kk = 0; kk < 16; kk++) {
            ulonglong2 a01 = *(const ulonglong2*)&As[cur][kk][ty * 8];
            ulonglong2 a23 = *(const ulonglong2*)&As[cur][kk][ty * 8 + 4];
            float4 wv = *(const float4*)&Ws[cur][kk][tx * 4];
            ull w0 = splat2(wv.x), w1 = splat2(wv.y), w2 = splat2(wv.z), w3 = splat2(wv.w);
            ffma2(c2[0][0], a01.x, w0); ffma2(c2[0][1], a01.x, w1);
            ffma2(c2[0][2], a01.x, w2); ffma2(c2[0][3], a01.x, w3);
            ffma2(c2[1][0], a01.y, w0); ffma2(c2[1][1], a01.y, w1);
            ffma2(c2[1][2], a01.y, w2); ffma2(c2[1][3], a01.y, w3);
            ffma2(c2[2][0], a23.x, w0); ffma2(c2[2][1], a23.x, w1);
            ffma2(c2[2][2], a23.x, w2); ffma2(c2[2][3], a23.x, w3);
            ffma2(c2[3][0], a23.y, w0); ffma2(c2[3][1], a23.y, w1);
            ffma2(c2[3][2], a23.y, w2); ffma2(c2[3][3], a23.y, w3);
        }
        if (more) { sts_tile(cur ^ 1); __syncthreads(); }
    }

    float bv[4];
#pragma unroll
    for (int j = 0; j < 4; j++) bv[j] = bias[n0 + tx * 4 + j];
#pragma unroll
    for (int ip = 0; ip < 4; ip++)
#pragma unroll
        for (int half = 0; half < 2; half++) {
            float r[4];
#pragma unroll
            for (int j = 0; j < 4; j++) {
                float lo, hi;
                unpack2(c2[ip][j], lo, hi);
                float v = (half == 0 ? lo : hi) + bv[j];
                r[j] = (ACT == 1) ? gelu_f(v) : v;
            }
            float4 v4 = make_float4(r[0], r[1], r[2], r[3]);
            int m = m0 + ty * 8 + ip * 2 + half;
            if (OUT_MODE == 0) *(float4*)(C + (size_t)m * ldc + n0 + tx * 4) = v4;
            else {
                int t = m >> 5, b = m & 31;
                *(float4*)(C + (size_t)b * (T_ * OUT_) + (size_t)t * OUT_ + tx * 4) = v4;
            }
        }
}

__global__ void hn_kernel(const float* __restrict__ hT, float* __restrict__ out)
{
    int i = blockIdx.x * 256 + threadIdx.x;
    int r = i >> 5, b = i & 31;
    out[(size_t)b * RES_ + r] = hT[i];
}

extern "C" void kernel_launch(void* const* d_in, const int* in_sizes, int n_in,
                              void* d_out, int out_size)
{
    const float* x   = (const float*)d_in[0];
    const float* Win = (const float*)d_in[1];
    const float* Wh  = (const float*)d_in[2];
    const float* W0  = (const float*)d_in[3];
    const float* b0  = (const float*)d_in[4];
    const float* W1  = (const float*)d_in[5];
    const float* b1  = (const float*)d_in[6];
    const float* W2  = (const float*)d_in[7];
    const float* b2  = (const float*)d_in[8];
    float*       out = (float*)d_out;

    float *UT, *a1, *a2;
    void *hi, *lo;
    unsigned* sf;
    cudaGetSymbolAddress((void**)&UT, g_UT);
    cudaGetSymbolAddress((void**)&a1, g_a1);
    cudaGetSymbolAddress((void**)&a2, g_a2);
    cudaGetSymbolAddress(&hi, g_hi);
    cudaGetSymbolAddress(&lo, g_lo);
    cudaGetSymbolAddress((void**)&sf, g_sf);

    cudaFuncSetAttribute(scan_mma_kernel, cudaFuncAttributeMaxDynamicSharedMemorySize, SCAN_SMEM);

    u_kernel<<<dim3(16, 1024), 256>>>(x, Win, UT);
    cudaMemsetAsync(hi, 0, 2ull * B_ * RES_ * sizeof(__nv_bfloat16));   // h(-1) = 0
    cudaMemsetAsync(lo, 0, 2ull * B_ * RES_ * sizeof(__nv_bfloat16));
    cudaMemsetAsync(sf, 0, 1024 * sizeof(unsigned));                    // flags reset per replay

    scan_mma_kernel<<<NCTA_, 256, SCAN_SMEM>>>(Wh, UT);

    gemm_kernel<0, 1, 0><<<dim3(BT_ / 128, HID_ / 64), 256>>>(UT, RES_, W0, b0, a1, HID_);
    gemm_kernel<1, 1, 0><<<dim3(BT_ / 128, HID_ / 64), 256>>>(a1, HID_, W1, b1, a2, HID_);
    gemm_kernel<1, 0, 1><<<dim3(BT_ / 128, 1), 256>>>(a2, HID_, W2, b2, out, OUT_);

    if (out_size >= (int)((size_t)B_ * T_ * OUT_ + (size_t)B_ * RES_))
        hn_kernel<<<RES_ * B_ / 256, 256>>>(UT + (size_t)(T_ - 1) * (RES_ * B_),
                                            out + (size_t)B_ * T_ * OUT_);
}

// round 16
// speedup vs baseline: 1.0084x; 1.0084x over previous
#include <cuda_runtime.h>
#include <cuda_bf16.h>
#include <math.h>
#include <stdint.h>

#define B_   32
#define T_   1024
#define IN_  64
#define RES_ 2048
#define HID_ 512
#define OUT_ 64
#define BT_  (B_ * T_)
#define NCTA_ 128

typedef unsigned long long ull;

// ---- fp32x2 (fp32 gemms) ----
__device__ __forceinline__ void ffma2(ull& d, ull a, ull b)
{ asm("fma.rn.f32x2 %0, %1, %2, %0;" : "+l"(d) : "l"(a), "l"(b)); }
__device__ __forceinline__ ull splat2(float h)
{ ull r; asm("mov.b64 %0, {%1, %1};" : "=l"(r) : "f"(h)); return r; }
__device__ __forceinline__ void unpack2(ull v, float& lo, float& hi)
{ asm("mov.b64 {%0, %1}, %2;" : "=f"(lo), "=f"(hi) : "l"(v)); }

// ---- acq/rel flags ----
__device__ __forceinline__ unsigned ld_acq(const unsigned* p)
{ unsigned v; asm volatile("ld.acquire.gpu.global.u32 %0, [%1];" : "=r"(v) : "l"(p)); return v; }
__device__ __forceinline__ void st_rel(unsigned* p, unsigned v)
{ asm volatile("st.release.gpu.global.u32 [%0], %1;" :: "l"(p), "r"(v) : "memory"); }

// ---- cp.async ----
__device__ __forceinline__ void cp16(uint32_t saddr, const void* g)
{ asm volatile("cp.async.cg.shared.global [%0], [%1], 16;" :: "r"(saddr), "l"(g) : "memory"); }
#define CP_COMMIT() asm volatile("cp.async.commit_group;" ::: "memory")
template <int N> __device__ __forceinline__ void cp_wait()
{ asm volatile("cp.async.wait_group %0;" :: "n"(N) : "memory"); }

// ---- warp mma bf16 m16n8k16 (validated R10/R12/R13) ----
__device__ __forceinline__ void mma16816(float c[4], const uint32_t a[4], const uint32_t b[2])
{
    asm volatile(
        "mma.sync.aligned.m16n8k16.row.col.f32.bf16.bf16.f32 "
        "{%0,%1,%2,%3},{%4,%5,%6,%7},{%8,%9},{%0,%1,%2,%3};"
        : "+f"(c[0]), "+f"(c[1]), "+f"(c[2]), "+f"(c[3])
        : "r"(a[0]), "r"(a[1]), "r"(a[2]), "r"(a[3]), "r"(b[0]), "r"(b[1]));
}

// ---- scratch ----
__device__ float          g_UT[(size_t)T_ * RES_ * B_];     // U[t][r][b]; hs only at t=T-1
__device__ __nv_bfloat16  g_hi[2ull * B_ * RES_];           // scan h hi ping-pong [buf][b][k]
__device__ __nv_bfloat16  g_lo[2ull * B_ * RES_];
__device__ __nv_bfloat16  g_hsh[(size_t)BT_ * RES_];        // hs hi, row-major [m][k], m=t*32+b
__device__ __nv_bfloat16  g_hsl[(size_t)BT_ * RES_];        // hs lo residual
__device__ __nv_bfloat16  g_w0h[(size_t)HID_ * RES_];       // W0 bf16 hi
__device__ __nv_bfloat16  g_w0l[(size_t)HID_ * RES_];       // W0 bf16 lo
__device__ unsigned       g_sf[1024];                       // flag[cta] @ cta*8
__device__ float          g_a1[(size_t)BT_ * HID_];
__device__ float          g_a2[(size_t)BT_ * HID_];

// ---------------- U = x @ W_in^T -> UT[t][r][b] ----------------
__global__ void __launch_bounds__(256) u_kernel(const float* __restrict__ x,
                                                const float* __restrict__ Win,
                                                float* __restrict__ UT)
{
    __shared__ float xS[IN_][B_];
    __shared__ float wS[IN_][128];
    const int t = blockIdx.y, R0 = blockIdx.x * 128, tid = threadIdx.x;
    {
        int b = tid >> 3, iq = (tid & 7) * 8;
        const float* src = x + (size_t)b * (T_ * IN_) + (size_t)t * IN_ + iq;
        float4 v0 = *(const float4*)src, v1 = *(const float4*)(src + 4);
        xS[iq+0][b]=v0.x; xS[iq+1][b]=v0.y; xS[iq+2][b]=v0.z; xS[iq+3][b]=v0.w;
        xS[iq+4][b]=v1.x; xS[iq+5][b]=v1.y; xS[iq+6][b]=v1.z; xS[iq+7][b]=v1.w;
    }
    {
        int r = tid >> 1, ih = (tid & 1) * 32;
        const float* src = Win + (size_t)(R0 + r) * IN_ + ih;
#pragma unroll
        for (int j = 0; j < 32; j += 4) {
            float4 v = *(const float4*)(src + j);
            wS[ih+j+0][r]=v.x; wS[ih+j+1][r]=v.y; wS[ih+j+2][r]=v.z; wS[ih+j+3][r]=v.w;
        }
    }
    __syncthreads();
    const int tx = tid & 7, ty = tid >> 3, b0 = tx * 4, r0 = ty * 4;
    float acc[4][4];
#pragma unroll
    for (int i = 0; i < 4; i++)
#pragma unroll
        for (int j = 0; j < 4; j++) acc[i][j] = 0.f;
#pragma unroll
    for (int i = 0; i < IN_; i++) {
        float4 xv = *(const float4*)&xS[i][b0];
        float4 wv = *(const float4*)&wS[i][r0];
        float xa[4] = {xv.x, xv.y, xv.z, xv.w}, wa[4] = {wv.x, wv.y, wv.z, wv.w};
#pragma unroll
        for (int ri = 0; ri < 4; ri++)
#pragma unroll
            for (int bi = 0; bi < 4; bi++) acc[ri][bi] = fmaf(wa[ri], xa[bi], acc[ri][bi]);
    }
    float* dst = UT + (size_t)t * (RES_ * B_);
#pragma unroll
    for (int ri = 0; ri < 4; ri++)
        *(float4*)(dst + (size_t)(R0 + r0 + ri) * B_ + b0) =
            make_float4(acc[ri][0], acc[ri][1], acc[ri][2], acc[ri][3]);
}

// ---------------- W0 -> bf16 hi/lo (once per launch) ----------------
__global__ void wcvt_kernel(const float* __restrict__ W,
                            __nv_bfloat16* __restrict__ wh,
                            __nv_bfloat16* __restrict__ wl, int n)
{
    int i = blockIdx.x * 256 + threadIdx.x;
    if (i < n) {
        float v = W[i];
        __nv_bfloat16 h = __float2bfloat16(v);
        wh[i] = h;
        wl[i] = __float2bfloat16(v - __bfloat162float(h));
    }
}

// ---------------- warp-MMA persistent scan (R13 verbatim + hs bf16 store) -----------
#define WROWB 4112
#define W_HI  0
#define W_LO  65792
#define BB    131584
#define BBSTR 17408
#define BROW  272
#define REDO  201216
#define SCAN_SMEM 205824

__global__ void __launch_bounds__(256) scan_mma_kernel(const float* __restrict__ Wh,
                                                       float* __restrict__ UT)
{
    extern __shared__ unsigned char smem_raw[];
    unsigned char* sw_hi = smem_raw + W_HI;
    unsigned char* sw_lo = smem_raw + W_LO;
    float* red = (float*)(smem_raw + REDO);
    const uint32_t sbase = (uint32_t)__cvta_generic_to_shared(smem_raw);

    const int tid  = threadIdx.x;
    const int w    = tid >> 5, lane = tid & 31;
    const int g    = lane >> 2, tq = lane & 3;
    const int nt   = w & 3;
    const int kh   = w >> 2;
    const int bid  = blockIdx.x;
    const int R0   = bid * 16;

    for (int r = 0; r < 16; r++) {
        const float* wrow = Wh + (size_t)(R0 + r) * RES_ + tid * 8;
#pragma unroll
        for (int j = 0; j < 4; j++) {
            float2 v = *(const float2*)(wrow + j * 2);
            __nv_bfloat16 h0 = __float2bfloat16(v.x), h1 = __float2bfloat16(v.y);
            __nv_bfloat16 l0 = __float2bfloat16(v.x - __bfloat162float(h0));
            __nv_bfloat16 l1 = __float2bfloat16(v.y - __bfloat162float(h1));
            unsigned hp = (unsigned)__bfloat16_as_ushort(h0) | ((unsigned)__bfloat16_as_ushort(h1) << 16);
            unsigned lp = (unsigned)__bfloat16_as_ushort(l0) | ((unsigned)__bfloat16_as_ushort(l1) << 16);
            int kbyte = (tid * 8 + j * 2) * 2;
            *(uint32_t*)(sw_hi + r * WROWB + kbyte) = hp;
            *(uint32_t*)(sw_lo + r * WROWB + kbyte) = lp;
        }
    }
    __syncthreads();

    const int ecol = tid & 31;
    const int erow = (tid >> 5) * 2;
    float hprev[2] = {0.f, 0.f};

    const int sr0 = (tid * 2) >> 4,     sg0 = (tid * 2) & 15;
    const int sr1 = (tid * 2 + 1) >> 4, sg1 = (tid * 2 + 1) & 15;

    for (int t = 0; t < T_; t++) {
        const int pr = t & 1;
        const int pw = pr ^ 1;
        const __nv_bfloat16* ghi = g_hi + (size_t)pr * (B_ * RES_);
        const __nv_bfloat16* glo = g_lo + (size_t)pr * (B_ * RES_);
        float* utr = UT + (size_t)t * (RES_ * B_);

        if (tid < NCTA_) {
            const unsigned* fp = g_sf + tid * 8;
            while ((int)(ld_acq(fp) - (unsigned)t) < 0) __nanosleep(32);
        }
        __syncthreads();

        auto stage = [&](int ck) {
            uint32_t bh = sbase + BB + (uint32_t)(ck & 3) * BBSTR;
            uint32_t bl = bh + 8704;
            cp16(bh + sr0 * BROW + sg0 * 16, ghi + (size_t)sr0 * RES_ + ck * 128 + sg0 * 8);
            cp16(bl + sr0 * BROW + sg0 * 16, glo + (size_t)sr0 * RES_ + ck * 128 + sg0 * 8);
            cp16(bh + sr1 * BROW + sg1 * 16, ghi + (size_t)sr1 * RES_ + ck * 128 + sg1 * 8);
            cp16(bl + sr1 * BROW + sg1 * 16, glo + (size_t)sr1 * RES_ + ck * 128 + sg1 * 8);
            CP_COMMIT();
        };

        float c[4] = {0.f, 0.f, 0.f, 0.f};
        stage(0); stage(1); stage(2);

        for (int ck = 0; ck < 16; ck++) {
            if (ck <= 13) cp_wait<2>(); else if (ck == 14) cp_wait<1>(); else cp_wait<0>();
            __syncthreads();
            if (ck + 3 < 16) stage(ck + 3);

            const unsigned char* bh = smem_raw + BB + (ck & 3) * BBSTR;
            const unsigned char* bl = bh + 8704;
#pragma unroll
            for (int i = 0; i < 4; i++) {
                int kk = kh * 4 + i;
                unsigned abase = (unsigned)g * WROWB + (unsigned)ck * 256 + kk * 32 + tq * 4;
                uint32_t ah[4], al[4], bhf[2], blf[2];
                ah[0] = *(const uint32_t*)(sw_hi + abase);
                ah[1] = *(const uint32_t*)(sw_hi + abase + 8 * WROWB);
                ah[2] = *(const uint32_t*)(sw_hi + abase + 16);
                ah[3] = *(const uint32_t*)(sw_hi + abase + 8 * WROWB + 16);
                al[0] = *(const uint32_t*)(sw_lo + abase);
                al[1] = *(const uint32_t*)(sw_lo + abase + 8 * WROWB);
                al[2] = *(const uint32_t*)(sw_lo + abase + 16);
                al[3] = *(const uint32_t*)(sw_lo + abase + 8 * WROWB + 16);
                unsigned bbase = (unsigned)(nt * 8 + g) * BROW + kk * 32 + tq * 4;
                bhf[0] = *(const uint32_t*)(bh + bbase);
                bhf[1] = *(const uint32_t*)(bh + bbase + 16);
                blf[0] = *(const uint32_t*)(bl + bbase);
                blf[1] = *(const uint32_t*)(bl + bbase + 16);
                mma16816(c, ah, bhf);
                mma16816(c, ah, blf);
                mma16816(c, al, bhf);
            }
            __syncthreads();
        }

#pragma unroll
        for (int i = 0; i < 4; i++) {
            int row = g + (i >> 1) * 8;
            int col = nt * 8 + tq * 2 + (i & 1);
            red[kh * 576 + row * 36 + col] = c[i];
        }
        __syncthreads();

        // epilogue: tanh -> publish gh + hs(bf16) -> bar -> flag
        {
            __nv_bfloat16* whi = g_hi + (size_t)pw * (B_ * RES_);
            __nv_bfloat16* wlo = g_lo + (size_t)pw * (B_ * RES_);
            float hn[2];
#pragma unroll
            for (int j = 0; j < 2; j++) {
                int row = erow + j;
                float s = red[row * 36 + ecol] + red[576 + row * 36 + ecol];
                float u = utr[(size_t)(R0 + row) * B_ + ecol];
                hn[j] = 0.5f * hprev[j] + 0.5f * tanhf(s + u);
                hprev[j] = hn[j];
            }
            __nv_bfloat16 h0 = __float2bfloat16(hn[0]), h1 = __float2bfloat16(hn[1]);
            __nv_bfloat16 l0 = __float2bfloat16(hn[0] - __bfloat162float(h0));
            __nv_bfloat16 l1 = __float2bfloat16(hn[1] - __bfloat162float(h1));
            unsigned hv = (unsigned)__bfloat16_as_ushort(h0) | ((unsigned)__bfloat16_as_ushort(h1) << 16);
            unsigned lv = (unsigned)__bfloat16_as_ushort(l0) | ((unsigned)__bfloat16_as_ushort(l1) << 16);
            size_t koff = (size_t)ecol * RES_ + R0 + erow;
            __stcg((unsigned*)(whi + koff), hv);
            __stcg((unsigned*)(wlo + koff), lv);
            // hs for readout: row-major [m][k], m = t*32 + b(ecol), k pair at R0+erow
            size_t hsoff = ((size_t)t * B_ + ecol) * RES_ + R0 + erow;
            __stcg((unsigned*)(g_hsh + hsoff), hv);
            __stcg((unsigned*)(g_hsl + hsoff), lv);
            if (t == T_ - 1) {   // fp32 h_n for hn_kernel
                utr[(size_t)(R0 + erow) * B_ + ecol]     = hn[0];
                utr[(size_t)(R0 + erow + 1) * B_ + ecol] = hn[1];
            }
        }
        __syncthreads();
        if (tid == 0) st_rel(g_sf + bid * 8, (unsigned)(t + 1));
    }
}

// ---------------- L0: bf16 split-MMA GEMM + bias + GELU -> fp32 a1 ----------------
// C[m][n] = gelu(sum_k hs[m][k]*W0[n][k] + b0[n]); split: hh + hl + lh.
// Tile 128x64, K-chunk 32, 8 warps (4m x 2n), warp tile 32x32. Double-buffered cp.async.
#define GB_BUF 30720    // per-buffer bytes: Ah 10240 | Al 10240 | Wh 5120 | Wl 5120
#define GROW 80         // smem row stride bytes (32 bf16 + pad)
#define GEMM_SMEM (2 * GB_BUF)

__global__ void __launch_bounds__(256) gemm_mma_kernel(
    const __nv_bfloat16* __restrict__ Ahg, const __nv_bfloat16* __restrict__ Alg,
    const __nv_bfloat16* __restrict__ Whg, const __nv_bfloat16* __restrict__ Wlg,
    const float* __restrict__ bias, float* __restrict__ C)
{
    extern __shared__ unsigned char sm[];
    const uint32_t sb = (uint32_t)__cvta_generic_to_shared(sm);
    const int tid = threadIdx.x, w = tid >> 5, lane = tid & 31;
    const int g = lane >> 2, tq = lane & 3;
    const int wm = w >> 1, wn = w & 1;
    const int m0 = blockIdx.x * 128, n0 = blockIdx.y * 64;

    const int arow = tid >> 1, as0 = (tid & 1) * 2;   // 2 A-segments per thread
    const int wrow = tid >> 2, ws = tid & 3;          // 1 W-segment per array

    auto stage = [&](int kc) {
        uint32_t base = sb + (uint32_t)(kc & 1) * GB_BUF;
        const __nv_bfloat16* ah = Ahg + (size_t)(m0 + arow) * RES_ + kc * 32 + as0 * 8;
        const __nv_bfloat16* al = Alg + (size_t)(m0 + arow) * RES_ + kc * 32 + as0 * 8;
        uint32_t ad = base + arow * GROW + as0 * 16;
        cp16(ad, ah);            cp16(ad + 16, ah + 8);
        cp16(ad + 10240, al);    cp16(ad + 10240 + 16, al + 8);
        cp16(base + 20480 + wrow * GROW + ws * 16, Whg + (size_t)(n0 + wrow) * RES_ + kc * 32 + ws * 8);
        cp16(base + 25600 + wrow * GROW + ws * 16, Wlg + (size_t)(n0 + wrow) * RES_ + kc * 32 + ws * 8);
        CP_COMMIT();
    };

    float c[2][4][4];
#pragma unroll
    for (int fa = 0; fa < 2; fa++)
#pragma unroll
        for (int fb = 0; fb < 4; fb++)
#pragma unroll
            for (int i = 0; i < 4; i++) c[fa][fb][i] = 0.f;

    stage(0);
    const int NCK = RES_ / 32;   // 64
    for (int ck = 0; ck < NCK; ck++) {
        if (ck + 1 < NCK) { stage(ck + 1); cp_wait<1>(); } else { cp_wait<0>(); }
        __syncthreads();

        const unsigned char* bp = sm + (ck & 1) * GB_BUF;
#pragma unroll
        for (int kk = 0; kk < 2; kk++) {
            uint32_t bh[4][2], bl[4][2];
#pragma unroll
            for (int fb = 0; fb < 4; fb++) {
                unsigned o = 20480u + (unsigned)(wn * 32 + fb * 8 + g) * GROW + kk * 32 + tq * 4;
                bh[fb][0] = *(const uint32_t*)(bp + o);
                bh[fb][1] = *(const uint32_t*)(bp + o + 16);
                bl[fb][0] = *(const uint32_t*)(bp + o + 5120);
                bl[fb][1] = *(const uint32_t*)(bp + o + 5120 + 16);
            }
#pragma unroll
            for (int fa = 0; fa < 2; fa++) {
                unsigned ao = (unsigned)(wm * 32 + fa * 16 + g) * GROW + kk * 32 + tq * 4;
                uint32_t ah[4], al[4];
                ah[0] = *(const uint32_t*)(bp + ao);
                ah[1] = *(const uint32_t*)(bp + ao + 8 * GROW);
                ah[2] = *(const uint32_t*)(bp + ao + 16);
                ah[3] = *(const uint32_t*)(bp + ao + 8 * GROW + 16);
                al[0] = *(const uint32_t*)(bp + ao + 10240);
                al[1] = *(const uint32_t*)(bp + ao + 10240 + 8 * GROW);
                al[2] = *(const uint32_t*)(bp + ao + 10240 + 16);
                al[3] = *(const uint32_t*)(bp + ao + 10240 + 8 * GROW + 16);
#pragma unroll
                for (int fb = 0; fb < 4; fb++) {
                    mma16816(c[fa][fb], ah, bh[fb]);
                    mma16816(c[fa][fb], ah, bl[fb]);
                    mma16816(c[fa][fb], al, bh[fb]);
                }
            }
        }
        __syncthreads();    // all reads of buf ck&1 done before restage
    }

    // epilogue: bias + exact GELU, fp32 float2 stores
#pragma unroll
    for (int fa = 0; fa < 2; fa++)
#pragma unroll
        for (int fb = 0; fb < 4; fb++) {
            int ncol = n0 + wn * 32 + fb * 8 + tq * 2;
            float b0v = bias[ncol], b1v = bias[ncol + 1];
#pragma unroll
            for (int half = 0; half < 2; half++) {
                int m = m0 + wm * 32 + fa * 16 + g + half * 8;
                float v0 = c[fa][fb][half * 2 + 0] + b0v;
                float v1 = c[fa][fb][half * 2 + 1] + b1v;
                v0 = 0.5f * v0 * (1.0f + erff(v0 * 0.70710678118654752f));
                v1 = 0.5f * v1 * (1.0f + erff(v1 * 0.70710678118654752f));
                *(float2*)(C + (size_t)m * HID_ + ncol) = make_float2(v0, v1);
            }
        }
}

// ---------------- fp32 gemm (R13) for L1/L2 ----------------
__device__ __forceinline__ float gelu_f(float v)
{ return 0.5f * v * (1.0f + erff(v * 0.70710678118654752f)); }

template <int ACT, int OUT_MODE>
__global__ void __launch_bounds__(256) gemm_kernel(const float* __restrict__ A, int K,
                                                   const float* __restrict__ W,
                                                   const float* __restrict__ bias,
                                                   float* __restrict__ C, int ldc)
{
    __shared__ float As[16][132];
    __shared__ float Ws[16][64];
    const int m0 = blockIdx.x * 128, n0 = blockIdx.y * 64, tid = threadIdx.x;
    const int tx = tid & 15, ty = tid >> 4;
    ull c2[4][4];
#pragma unroll
    for (int i = 0; i < 4; i++)
#pragma unroll
        for (int j = 0; j < 4; j++) c2[i][j] = 0ull;

    for (int k0 = 0; k0 < K; k0 += 16) {
        {
            int mm = tid >> 1, kk = (tid & 1) * 8;
            const float* src = A + (size_t)(m0 + mm) * K + k0 + kk;
            float4 v0 = *(const float4*)src, v1 = *(const float4*)(src + 4);
            As[kk+0][mm]=v0.x; As[kk+1][mm]=v0.y; As[kk+2][mm]=v0.z; As[kk+3][mm]=v0.w;
            As[kk+4][mm]=v1.x; As[kk+5][mm]=v1.y; As[kk+6][mm]=v1.z; As[kk+7][mm]=v1.w;
        }
        {
            int n = tid >> 2, kq = (tid & 3) * 4;
            float4 v = *(const float4*)(W + (size_t)(n0 + n) * K + k0 + kq);
            Ws[kq+0][n]=v.x; Ws[kq+1][n]=v.y; Ws[kq+2][n]=v.z; Ws[kq+3][n]=v.w;
        }
        __syncthreads();
#pragma unroll
        for (int kk = 0; kk < 16; kk++) {
            ulonglong2 a01 = *(const ulonglong2*)&As[kk][ty * 8];
            ulonglong2 a23 = *(const ulonglong2*)&As[kk][ty * 8 + 4];
            float4 wv = *(const float4*)&Ws[kk][tx * 4];
            ull w0 = splat2(wv.x), w1 = splat2(wv.y), w2 = splat2(wv.z), w3 = splat2(wv.w);
            ffma2(c2[0][0], a01.x, w0); ffma2(c2[0][1], a01.x, w1);
            ffma2(c2[0][2], a01.x, w2); ffma2(c2[0][3], a01.x, w3);
            ffma2(c2[1][0], a01.y, w0); ffma2(c2[1][1], a01.y, w1);
            ffma2(c2[1][2], a01.y, w2); ffma2(c2[1][3], a01.y, w3);
            ffma2(c2[2][0], a23.x, w0); ffma2(c2[2][1], a23.x, w1);
            ffma2(c2[2][2], a23.x, w2); ffma2(c2[2][3], a23.x, w3);
            ffma2(c2[3][0], a23.y, w0); ffma2(c2[3][1], a23.y, w1);
            ffma2(c2[3][2], a23.y, w2); ffma2(c2[3][3], a23.y, w3);
        }
        __syncthreads();
    }

    float bv[4];
#pragma unroll
    for (int j = 0; j < 4; j++) bv[j] = bias[n0 + tx * 4 + j];
#pragma unroll
    for (int ip = 0; ip < 4; ip++)
#pragma unroll
        for (int half = 0; half < 2; half++) {
            float r[4];
#pragma unroll
            for (int j = 0; j < 4; j++) {
                float lo, hi;
                unpack2(c2[ip][j], lo, hi);
                float v = (half == 0 ? lo : hi) + bv[j];
                r[j] = (ACT == 1) ? gelu_f(v) : v;
            }
            float4 v4 = make_float4(r[0], r[1], r[2], r[3]);
            int m = m0 + ty * 8 + ip * 2 + half;
            if (OUT_MODE == 0) *(float4*)(C + (size_t)m * ldc + n0 + tx * 4) = v4;
            else {
                int t = m >> 5, b = m & 31;
                *(float4*)(C + (size_t)b * (T_ * OUT_) + (size_t)t * OUT_ + tx * 4) = v4;
            }
        }
}

__global__ void hn_kernel(const float* __restrict__ hT, float* __restrict__ out)
{
    int i = blockIdx.x * 256 + threadIdx.x;
    int r = i >> 5, b = i & 31;
    out[(size_t)b * RES_ + r] = hT[i];
}

extern "C" void kernel_launch(void* const* d_in, const int* in_sizes, int n_in,
                              void* d_out, int out_size)
{
    const float* x   = (const float*)d_in[0];
    const float* Win = (const float*)d_in[1];
    const float* Wh  = (const float*)d_in[2];
    const float* W0  = (const float*)d_in[3];
    const float* b0  = (const float*)d_in[4];
    const float* W1  = (const float*)d_in[5];
    const float* b1  = (const float*)d_in[6];
    const float* W2  = (const float*)d_in[7];
    const float* b2  = (const float*)d_in[8];
    float*       out = (float*)d_out;

    float *UT, *a1, *a2;
    void *hi, *lo, *hsh, *hsl, *w0h, *w0l;
    unsigned* sf;
    cudaGetSymbolAddress((void**)&UT, g_UT);
    cudaGetSymbolAddress((void**)&a1, g_a1);
    cudaGetSymbolAddress((void**)&a2, g_a2);
    cudaGetSymbolAddress(&hi, g_hi);
    cudaGetSymbolAddress(&lo, g_lo);
    cudaGetSymbolAddress(&hsh, g_hsh);
    cudaGetSymbolAddress(&hsl, g_hsl);
    cudaGetSymbolAddress(&w0h, g_w0h);
    cudaGetSymbolAddress(&w0l, g_w0l);
    cudaGetSymbolAddress((void**)&sf, g_sf);

    cudaFuncSetAttribute(scan_mma_kernel, cudaFuncAttributeMaxDynamicSharedMemorySize, SCAN_SMEM);
    cudaFuncSetAttribute(gemm_mma_kernel, cudaFuncAttributeMaxDynamicSharedMemorySize, GEMM_SMEM);

    u_kernel<<<dim3(16, 1024), 256>>>(x, Win, UT);
    wcvt_kernel<<<(HID_ * RES_ + 255) / 256, 256>>>(W0, (__nv_bfloat16*)w0h, (__nv_bfloat16*)w0l,
                                                    HID_ * RES_);
    cudaMemsetAsync(hi, 0, 2ull * B_ * RES_ * sizeof(__nv_bfloat16));
    cudaMemsetAsync(lo, 0, 2ull * B_ * RES_ * sizeof(__nv_bfloat16));
    cudaMemsetAsync(sf, 0, 1024 * sizeof(unsigned));

    scan_mma_kernel<<<NCTA_, 256, SCAN_SMEM>>>(Wh, UT);

    gemm_mma_kernel<<<dim3(BT_ / 128, HID_ / 64), 256, GEMM_SMEM>>>(
        (const __nv_bfloat16*)hsh, (const __nv_bfloat16*)hsl,
        (const __nv_bfloat16*)w0h, (const __nv_bfloat16*)w0l, b0, a1);
    gemm_kernel<1, 0><<<dim3(BT_ / 128, HID_ / 64), 256>>>(a1, HID_, W1, b1, a2, HID_);
    gemm_kernel<0, 1><<<dim3(BT_ / 128, 1), 256>>>(a2, HID_, W2, b2, out, OUT_);

    if (out_size >= (int)((size_t)B_ * T_ * OUT_ + (size_t)B_ * RES_))
        hn_kernel<<<RES_ * B_ / 256, 256>>>(UT + (size_t)(T_ - 1) * (RES_ * B_),
                                            out + (size_t)B_ * T_ * OUT_);
}

// round 17
// speedup vs baseline: 1.0433x; 1.0346x over previous
#include <cuda_runtime.h>
#include <cuda_bf16.h>
#include <math.h>
#include <stdint.h>

#define B_   32
#define T_   1024
#define IN_  64
#define RES_ 2048
#define HID_ 512
#define OUT_ 64
#define BT_  (B_ * T_)
#define NCTA_ 128

typedef unsigned long long ull;

// ---- fp32x2 (fp32 gemms) ----
__device__ __forceinline__ void ffma2(ull& d, ull a, ull b)
{ asm("fma.rn.f32x2 %0, %1, %2, %0;" : "+l"(d) : "l"(a), "l"(b)); }
__device__ __forceinline__ ull splat2(float h)
{ ull r; asm("mov.b64 %0, {%1, %1};" : "=l"(r) : "f"(h)); return r; }
__device__ __forceinline__ void unpack2(ull v, float& lo, float& hi)
{ asm("mov.b64 {%0, %1}, %2;" : "=f"(lo), "=f"(hi) : "l"(v)); }

// ---- acq/rel flags ----
__device__ __forceinline__ unsigned ld_acq(const unsigned* p)
{ unsigned v; asm volatile("ld.acquire.gpu.global.u32 %0, [%1];" : "=r"(v) : "l"(p)); return v; }
__device__ __forceinline__ void st_rel(unsigned* p, unsigned v)
{ asm volatile("st.release.gpu.global.u32 [%0], %1;" :: "l"(p), "r"(v) : "memory"); }

// ---- cp.async ----
__device__ __forceinline__ void cp16(uint32_t saddr, const void* g)
{ asm volatile("cp.async.cg.shared.global [%0], [%1], 16;" :: "r"(saddr), "l"(g) : "memory"); }
#define CP_COMMIT() asm volatile("cp.async.commit_group;" ::: "memory")
template <int N> __device__ __forceinline__ void cp_wait()
{ asm volatile("cp.async.wait_group %0;" :: "n"(N) : "memory"); }

// ---- warp mma bf16 m16n8k16 (validated R10/R12/R13/R16) ----
__device__ __forceinline__ void mma16816(float c[4], const uint32_t a[4], const uint32_t b[2])
{
    asm volatile(
        "mma.sync.aligned.m16n8k16.row.col.f32.bf16.bf16.f32 "
        "{%0,%1,%2,%3},{%4,%5,%6,%7},{%8,%9},{%0,%1,%2,%3};"
        : "+f"(c[0]), "+f"(c[1]), "+f"(c[2]), "+f"(c[3])
        : "r"(a[0]), "r"(a[1]), "r"(a[2]), "r"(a[3]), "r"(b[0]), "r"(b[1]));
}

// ---- scratch ----
__device__ float          g_UT[(size_t)T_ * RES_ * B_];     // U[t][r][b]; hs only at t=T-1
__device__ __nv_bfloat16  g_hi[2ull * B_ * RES_];           // scan h hi ping-pong [buf][b][k]
__device__ __nv_bfloat16  g_lo[2ull * B_ * RES_];
__device__ __nv_bfloat16  g_hsh[(size_t)BT_ * RES_];        // hs hi, row-major [m][k], m=t*32+b
__device__ __nv_bfloat16  g_hsl[(size_t)BT_ * RES_];        // hs lo residual
__device__ __nv_bfloat16  g_w0h[(size_t)HID_ * RES_];       // W0 bf16 hi
__device__ __nv_bfloat16  g_w0l[(size_t)HID_ * RES_];       // W0 bf16 lo
__device__ unsigned       g_sf[1024];                       // flag[cta] @ cta*8
__device__ float          g_a1[(size_t)BT_ * HID_];
__device__ float          g_a2[(size_t)BT_ * HID_];

// ---------------- U = x @ W_in^T -> UT[t][r][b] ----------------
__global__ void __launch_bounds__(256) u_kernel(const float* __restrict__ x,
                                                const float* __restrict__ Win,
                                                float* __restrict__ UT)
{
    __shared__ float xS[IN_][B_];
    __shared__ float wS[IN_][128];
    const int t = blockIdx.y, R0 = blockIdx.x * 128, tid = threadIdx.x;
    {
        int b = tid >> 3, iq = (tid & 7) * 8;
        const float* src = x + (size_t)b * (T_ * IN_) + (size_t)t * IN_ + iq;
        float4 v0 = *(const float4*)src, v1 = *(const float4*)(src + 4);
        xS[iq+0][b]=v0.x; xS[iq+1][b]=v0.y; xS[iq+2][b]=v0.z; xS[iq+3][b]=v0.w;
        xS[iq+4][b]=v1.x; xS[iq+5][b]=v1.y; xS[iq+6][b]=v1.z; xS[iq+7][b]=v1.w;
    }
    {
        int r = tid >> 1, ih = (tid & 1) * 32;
        const float* src = Win + (size_t)(R0 + r) * IN_ + ih;
#pragma unroll
        for (int j = 0; j < 32; j += 4) {
            float4 v = *(const float4*)(src + j);
            wS[ih+j+0][r]=v.x; wS[ih+j+1][r]=v.y; wS[ih+j+2][r]=v.z; wS[ih+j+3][r]=v.w;
        }
    }
    __syncthreads();
    const int tx = tid & 7, ty = tid >> 3, b0 = tx * 4, r0 = ty * 4;
    float acc[4][4];
#pragma unroll
    for (int i = 0; i < 4; i++)
#pragma unroll
        for (int j = 0; j < 4; j++) acc[i][j] = 0.f;
#pragma unroll
    for (int i = 0; i < IN_; i++) {
        float4 xv = *(const float4*)&xS[i][b0];
        float4 wv = *(const float4*)&wS[i][r0];
        float xa[4] = {xv.x, xv.y, xv.z, xv.w}, wa[4] = {wv.x, wv.y, wv.z, wv.w};
#pragma unroll
        for (int ri = 0; ri < 4; ri++)
#pragma unroll
            for (int bi = 0; bi < 4; bi++) acc[ri][bi] = fmaf(wa[ri], xa[bi], acc[ri][bi]);
    }
    float* dst = UT + (size_t)t * (RES_ * B_);
#pragma unroll
    for (int ri = 0; ri < 4; ri++)
        *(float4*)(dst + (size_t)(R0 + r0 + ri) * B_ + b0) =
            make_float4(acc[ri][0], acc[ri][1], acc[ri][2], acc[ri][3]);
}

// ---------------- W0 -> bf16 hi/lo (once per launch) ----------------
__global__ void wcvt_kernel(const float* __restrict__ W,
                            __nv_bfloat16* __restrict__ wh,
                            __nv_bfloat16* __restrict__ wl, int n)
{
    int i = blockIdx.x * 256 + threadIdx.x;
    if (i < n) {
        float v = W[i];
        __nv_bfloat16 h = __float2bfloat16(v);
        wh[i] = h;
        wl[i] = __float2bfloat16(v - __bfloat162float(h));
    }
}

// ---------------- warp-MMA persistent scan (R13 pipeline + coalesced hs) -----------
#define WROWB 4112
#define W_HI  0
#define W_LO  65792
#define BB    131584
#define BBSTR 17408
#define BROW  272
#define REDO  201216
#define HSS   205824            // hs staging: hi 1KB @ +0, lo 1KB @ +1024
#define SCAN_SMEM 207872

__global__ void __launch_bounds__(256) scan_mma_kernel(const float* __restrict__ Wh,
                                                       float* __restrict__ UT)
{
    extern __shared__ unsigned char smem_raw[];
    unsigned char* sw_hi = smem_raw + W_HI;
    unsigned char* sw_lo = smem_raw + W_LO;
    float* red = (float*)(smem_raw + REDO);
    const uint32_t sbase = (uint32_t)__cvta_generic_to_shared(smem_raw);

    const int tid  = threadIdx.x;
    const int w    = tid >> 5, lane = tid & 31;
    const int g    = lane >> 2, tq = lane & 3;
    const int nt   = w & 3;
    const int kh   = w >> 2;
    const int bid  = blockIdx.x;
    const int R0   = bid * 16;

    for (int r = 0; r < 16; r++) {
        const float* wrow = Wh + (size_t)(R0 + r) * RES_ + tid * 8;
#pragma unroll
        for (int j = 0; j < 4; j++) {
            float2 v = *(const float2*)(wrow + j * 2);
            __nv_bfloat16 h0 = __float2bfloat16(v.x), h1 = __float2bfloat16(v.y);
            __nv_bfloat16 l0 = __float2bfloat16(v.x - __bfloat162float(h0));
            __nv_bfloat16 l1 = __float2bfloat16(v.y - __bfloat162float(h1));
            unsigned hp = (unsigned)__bfloat16_as_ushort(h0) | ((unsigned)__bfloat16_as_ushort(h1) << 16);
            unsigned lp = (unsigned)__bfloat16_as_ushort(l0) | ((unsigned)__bfloat16_as_ushort(l1) << 16);
            int kbyte = (tid * 8 + j * 2) * 2;
            *(uint32_t*)(sw_hi + r * WROWB + kbyte) = hp;
            *(uint32_t*)(sw_lo + r * WROWB + kbyte) = lp;
        }
    }
    __syncthreads();

    const int ecol = tid & 31;
    const int erow = (tid >> 5) * 2;
    float hprev[2] = {0.f, 0.f};

    const int sr0 = (tid * 2) >> 4,     sg0 = (tid * 2) & 15;
    const int sr1 = (tid * 2 + 1) >> 4, sg1 = (tid * 2 + 1) & 15;

    for (int t = 0; t < T_; t++) {
        const int pr = t & 1;
        const int pw = pr ^ 1;
        const __nv_bfloat16* ghi = g_hi + (size_t)pr * (B_ * RES_);
        const __nv_bfloat16* glo = g_lo + (size_t)pr * (B_ * RES_);
        float* utr = UT + (size_t)t * (RES_ * B_);

        if (tid < NCTA_) {
            const unsigned* fp = g_sf + tid * 8;
            while ((int)(ld_acq(fp) - (unsigned)t) < 0) __nanosleep(32);
        }
        __syncthreads();

        auto stage = [&](int ck) {
            uint32_t bh = sbase + BB + (uint32_t)(ck & 3) * BBSTR;
            uint32_t bl = bh + 8704;
            cp16(bh + sr0 * BROW + sg0 * 16, ghi + (size_t)sr0 * RES_ + ck * 128 + sg0 * 8);
            cp16(bl + sr0 * BROW + sg0 * 16, glo + (size_t)sr0 * RES_ + ck * 128 + sg0 * 8);
            cp16(bh + sr1 * BROW + sg1 * 16, ghi + (size_t)sr1 * RES_ + ck * 128 + sg1 * 8);
            cp16(bl + sr1 * BROW + sg1 * 16, glo + (size_t)sr1 * RES_ + ck * 128 + sg1 * 8);
            CP_COMMIT();
        };

        float c[4] = {0.f, 0.f, 0.f, 0.f};
        stage(0); stage(1); stage(2);

        for (int ck = 0; ck < 16; ck++) {
            if (ck <= 13) cp_wait<2>(); else if (ck == 14) cp_wait<1>(); else cp_wait<0>();
            __syncthreads();
            if (ck + 3 < 16) stage(ck + 3);

            const unsigned char* bh = smem_raw + BB + (ck & 3) * BBSTR;
            const unsigned char* bl = bh + 8704;
#pragma unroll
            for (int i = 0; i < 4; i++) {
                int kk = kh * 4 + i;
                unsigned abase = (unsigned)g * WROWB + (unsigned)ck * 256 + kk * 32 + tq * 4;
                uint32_t ah[4], al[4], bhf[2], blf[2];
                ah[0] = *(const uint32_t*)(sw_hi + abase);
                ah[1] = *(const uint32_t*)(sw_hi + abase + 8 * WROWB);
                ah[2] = *(const uint32_t*)(sw_hi + abase + 16);
                ah[3] = *(const uint32_t*)(sw_hi + abase + 8 * WROWB + 16);
                al[0] = *(const uint32_t*)(sw_lo + abase);
                al[1] = *(const uint32_t*)(sw_lo + abase + 8 * WROWB);
                al[2] = *(const uint32_t*)(sw_lo + abase + 16);
                al[3] = *(const uint32_t*)(sw_lo + abase + 8 * WROWB + 16);
                unsigned bbase = (unsigned)(nt * 8 + g) * BROW + kk * 32 + tq * 4;
                bhf[0] = *(const uint32_t*)(bh + bbase);
                bhf[1] = *(const uint32_t*)(bh + bbase + 16);
                blf[0] = *(const uint32_t*)(bl + bbase);
                blf[1] = *(const uint32_t*)(bl + bbase + 16);
                mma16816(c, ah, bhf);
                mma16816(c, ah, blf);
                mma16816(c, al, bhf);
            }
            __syncthreads();
        }

#pragma unroll
        for (int i = 0; i < 4; i++) {
            int row = g + (i >> 1) * 8;
            int col = nt * 8 + tq * 2 + (i & 1);
            red[kh * 576 + row * 36 + col] = c[i];
        }
        __syncthreads();

        // epilogue: tanh -> publish gh (critical) + stage hs in SMEM -> bar -> flag
        {
            __nv_bfloat16* whi = g_hi + (size_t)pw * (B_ * RES_);
            __nv_bfloat16* wlo = g_lo + (size_t)pw * (B_ * RES_);
            float hn[2];
#pragma unroll
            for (int j = 0; j < 2; j++) {
                int row = erow + j;
                float s = red[row * 36 + ecol] + red[576 + row * 36 + ecol];
                float u = utr[(size_t)(R0 + row) * B_ + ecol];
                hn[j] = 0.5f * hprev[j] + 0.5f * tanhf(s + u);
                hprev[j] = hn[j];
            }
            __nv_bfloat16 h0 = __float2bfloat16(hn[0]), h1 = __float2bfloat16(hn[1]);
            __nv_bfloat16 l0 = __float2bfloat16(hn[0] - __bfloat162float(h0));
            __nv_bfloat16 l1 = __float2bfloat16(hn[1] - __bfloat162float(h1));
            unsigned hv = (unsigned)__bfloat16_as_ushort(h0) | ((unsigned)__bfloat16_as_ushort(h1) << 16);
            unsigned lv = (unsigned)__bfloat16_as_ushort(l0) | ((unsigned)__bfloat16_as_ushort(l1) << 16);
            size_t koff = (size_t)ecol * RES_ + R0 + erow;
            __stcg((unsigned*)(whi + koff), hv);
            __stcg((unsigned*)(wlo + koff), lv);
            // stage hs rows in SMEM: stg[b][k16] (hi @ HSS, lo @ HSS+1024)
            *(uint32_t*)(smem_raw + HSS + ecol * 32 + erow * 2)        = hv;
            *(uint32_t*)(smem_raw + HSS + 1024 + ecol * 32 + erow * 2) = lv;
            if (t == T_ - 1) {   // fp32 h_n for hn_kernel
                utr[(size_t)(R0 + erow) * B_ + ecol]     = hn[0];
                utr[(size_t)(R0 + erow + 1) * B_ + ecol] = hn[1];
            }
        }
        __syncthreads();
        if (tid == 0) st_rel(g_sf + bid * 8, (unsigned)(t + 1));

        // hs emit: coalesced 16B chunks, OFF the inter-CTA critical path
        if (tid < 128) {
            int b = tid >> 2, cix = tid & 3;
            int arr = cix >> 1, o16 = cix & 1;
            uint4 v = *(const uint4*)(smem_raw + HSS + arr * 1024 + b * 32 + o16 * 16);
            __nv_bfloat16* dst = arr ? g_hsl : g_hsh;
            __stcg((uint4*)(dst + ((size_t)t * B_ + b) * RES_ + R0 + o16 * 8), v);
        }
        // stg reuse next step is ordered by the chunk-loop __syncthreads
    }
}

// ---------------- L0: bf16 split-MMA GEMM + bias + GELU -> fp32 a1 ----------------
// grid (n-tiles, m-tiles): adjacent CTAs share the A tile -> A read once from DRAM.
#define GB_BUF 30720
#define GROW 80
#define GEMM_SMEM (2 * GB_BUF)

__global__ void __launch_bounds__(256) gemm_mma_kernel(
    const __nv_bfloat16* __restrict__ Ahg, const __nv_bfloat16* __restrict__ Alg,
    const __nv_bfloat16* __restrict__ Whg, const __nv_bfloat16* __restrict__ Wlg,
    const float* __restrict__ bias, float* __restrict__ C)
{
    extern __shared__ unsigned char sm[];
    const uint32_t sb = (uint32_t)__cvta_generic_to_shared(sm);
    const int tid = threadIdx.x, w = tid >> 5, lane = tid & 31;
    const int g = lane >> 2, tq = lane & 3;
    const int wm = w >> 1, wn = w & 1;
    const int m0 = blockIdx.y * 128, n0 = blockIdx.x * 64;   // SWAPPED axes

    const int arow = tid >> 1, as0 = (tid & 1) * 2;
    const int wrow = tid >> 2, ws = tid & 3;

    auto stage = [&](int kc) {
        uint32_t base = sb + (uint32_t)(kc & 1) * GB_BUF;
        const __nv_bfloat16* ah = Ahg + (size_t)(m0 + arow) * RES_ + kc * 32 + as0 * 8;
        const __nv_bfloat16* al = Alg + (size_t)(m0 + arow) * RES_ + kc * 32 + as0 * 8;
        uint32_t ad = base + arow * GROW + as0 * 16;
        cp16(ad, ah);            cp16(ad + 16, ah + 8);
        cp16(ad + 10240, al);    cp16(ad + 10240 + 16, al + 8);
        cp16(base + 20480 + wrow * GROW + ws * 16, Whg + (size_t)(n0 + wrow) * RES_ + kc * 32 + ws * 8);
        cp16(base + 25600 + wrow * GROW + ws * 16, Wlg + (size_t)(n0 + wrow) * RES_ + kc * 32 + ws * 8);
        CP_COMMIT();
    };

    float c[2][4][4];
#pragma unroll
    for (int fa = 0; fa < 2; fa++)
#pragma unroll
        for (int fb = 0; fb < 4; fb++)
#pragma unroll
            for (int i = 0; i < 4; i++) c[fa][fb][i] = 0.f;

    stage(0);
    const int NCK = RES_ / 32;
    for (int ck = 0; ck < NCK; ck++) {
        if (ck + 1 < NCK) { stage(ck + 1); cp_wait<1>(); } else { cp_wait<0>(); }
        __syncthreads();

        const unsigned char* bp = sm + (ck & 1) * GB_BUF;
#pragma unroll
        for (int kk = 0; kk < 2; kk++) {
            uint32_t bh[4][2], bl[4][2];
#pragma unroll
            for (int fb = 0; fb < 4; fb++) {
                unsigned o = 20480u + (unsigned)(wn * 32 + fb * 8 + g) * GROW + kk * 32 + tq * 4;
                bh[fb][0] = *(const uint32_t*)(bp + o);
                bh[fb][1] = *(const uint32_t*)(bp + o + 16);
                bl[fb][0] = *(const uint32_t*)(bp + o + 5120);
                bl[fb][1] = *(const uint32_t*)(bp + o + 5120 + 16);
            }
#pragma unroll
            for (int fa = 0; fa < 2; fa++) {
                unsigned ao = (unsigned)(wm * 32 + fa * 16 + g) * GROW + kk * 32 + tq * 4;
                uint32_t ah[4], al[4];
                ah[0] = *(const uint32_t*)(bp + ao);
                ah[1] = *(const uint32_t*)(bp + ao + 8 * GROW);
                ah[2] = *(const uint32_t*)(bp + ao + 16);
                ah[3] = *(const uint32_t*)(bp + ao + 8 * GROW + 16);
                al[0] = *(const uint32_t*)(bp + ao + 10240);
                al[1] = *(const uint32_t*)(bp + ao + 10240 + 8 * GROW);
                al[2] = *(const uint32_t*)(bp + ao + 10240 + 16);
                al[3] = *(const uint32_t*)(bp + ao + 10240 + 8 * GROW + 16);
#pragma unroll
                for (int fb = 0; fb < 4; fb++) {
                    mma16816(c[fa][fb], ah, bh[fb]);
                    mma16816(c[fa][fb], ah, bl[fb]);
                    mma16816(c[fa][fb], al, bh[fb]);
                }
            }
        }
        __syncthreads();
    }

#pragma unroll
    for (int fa = 0; fa < 2; fa++)
#pragma unroll
        for (int fb = 0; fb < 4; fb++) {
            int ncol = n0 + wn * 32 + fb * 8 + tq * 2;
            float b0v = bias[ncol], b1v = bias[ncol + 1];
#pragma unroll
            for (int half = 0; half < 2; half++) {
                int m = m0 + wm * 32 + fa * 16 + g + half * 8;
                float v0 = c[fa][fb][half * 2 + 0] + b0v;
                float v1 = c[fa][fb][half * 2 + 1] + b1v;
                v0 = 0.5f * v0 * (1.0f + erff(v0 * 0.70710678118654752f));
                v1 = 0.5f * v1 * (1.0f + erff(v1 * 0.70710678118654752f));
                *(float2*)(C + (size_t)m * HID_ + ncol) = make_float2(v0, v1);
            }
        }
}

// ---------------- fp32 gemm for L1/L2 ----------------
__device__ __forceinline__ float gelu_f(float v)
{ return 0.5f * v * (1.0f + erff(v * 0.70710678118654752f)); }

template <int ACT, int OUT_MODE>
__global__ void __launch_bounds__(256) gemm_kernel(const float* __restrict__ A, int K,
                                                   const float* __restrict__ W,
                                                   const float* __restrict__ bias,
                                                   float* __restrict__ C, int ldc)
{
    __shared__ float As[16][132];
    __shared__ float Ws[16][64];
    const int m0 = blockIdx.x * 128, n0 = blockIdx.y * 64, tid = threadIdx.x;
    const int tx = tid & 15, ty = tid >> 4;
    ull c2[4][4];
#pragma unroll
    for (int i = 0; i < 4; i++)
#pragma unroll
        for (int j = 0; j < 4; j++) c2[i][j] = 0ull;

    for (int k0 = 0; k0 < K; k0 += 16) {
        {
            int mm = tid >> 1, kk = (tid & 1) * 8;
            const float* src = A + (size_t)(m0 + mm) * K + k0 + kk;
            float4 v0 = *(const float4*)src, v1 = *(const float4*)(src + 4);
            As[kk+0][mm]=v0.x; As[kk+1][mm]=v0.y; As[kk+2][mm]=v0.z; As[kk+3][mm]=v0.w;
            As[kk+4][mm]=v1.x; As[kk+5][mm]=v1.y; As[kk+6][mm]=v1.z; As[kk+7][mm]=v1.w;
        }
        {
            int n = tid >> 2, kq = (tid & 3) * 4;
            float4 v = *(const float4*)(W + (size_t)(n0 + n) * K + k0 + kq);
            Ws[kq+0][n]=v.x; Ws[kq+1][n]=v.y; Ws[kq+2][n]=v.z; Ws[kq+3][n]=v.w;
        }
        __syncthreads();
#pragma unroll
        for (int kk = 0; kk < 16; kk++) {
            ulonglong2 a01 = *(const ulonglong2*)&As[kk][ty * 8];
            ulonglong2 a23 = *(const ulonglong2*)&As[kk][ty * 8 + 4];
            float4 wv = *(const float4*)&Ws[kk][tx * 4];
            ull w0 = splat2(wv.x), w1 = splat2(wv.y), w2 = splat2(wv.z), w3 = splat2(wv.w);
            ffma2(c2[0][0], a01.x, w0); ffma2(c2[0][1], a01.x, w1);
            ffma2(c2[0][2], a01.x, w2); ffma2(c2[0][3], a01.x, w3);
            ffma2(c2[1][0], a01.y, w0); ffma2(c2[1][1], a01.y, w1);
            ffma2(c2[1][2], a01.y, w2); ffma2(c2[1][3], a01.y, w3);
            ffma2(c2[2][0], a23.x, w0); ffma2(c2[2][1], a23.x, w1);
            ffma2(c2[2][2], a23.x, w2); ffma2(c2[2][3], a23.x, w3);
            ffma2(c2[3][0], a23.y, w0); ffma2(c2[3][1], a23.y, w1);
            ffma2(c2[3][2], a23.y, w2); ffma2(c2[3][3], a23.y, w3);
        }
        __syncthreads();
    }

    float bv[4];
#pragma unroll
    for (int j = 0; j < 4; j++) bv[j] = bias[n0 + tx * 4 + j];
#pragma unroll
    for (int ip = 0; ip < 4; ip++)
#pragma unroll
        for (int half = 0; half < 2; half++) {
            float r[4];
#pragma unroll
            for (int j = 0; j < 4; j++) {
                float lo, hi;
                unpack2(c2[ip][j], lo, hi);
                float v = (half == 0 ? lo : hi) + bv[j];
                r[j] = (ACT == 1) ? gelu_f(v) : v;
            }
            float4 v4 = make_float4(r[0], r[1], r[2], r[3]);
            int m = m0 + ty * 8 + ip * 2 + half;
            if (OUT_MODE == 0) *(float4*)(C + (size_t)m * ldc + n0 + tx * 4) = v4;
            else {
                int t = m >> 5, b = m & 31;
                *(float4*)(C + (size_t)b * (T_ * OUT_) + (size_t)t * OUT_ + tx * 4) = v4;
            }
        }
}

__global__ void hn_kernel(const float* __restrict__ hT, float* __restrict__ out)
{
    int i = blockIdx.x * 256 + threadIdx.x;
    int r = i >> 5, b = i & 31;
    out[(size_t)b * RES_ + r] = hT[i];
}

extern "C" void kernel_launch(void* const* d_in, const int* in_sizes, int n_in,
                              void* d_out, int out_size)
{
    const float* x   = (const float*)d_in[0];
    const float* Win = (const float*)d_in[1];
    const float* Wh  = (const float*)d_in[2];
    const float* W0  = (const float*)d_in[3];
    const float* b0  = (const float*)d_in[4];
    const float* W1  = (const float*)d_in[5];
    const float* b1  = (const float*)d_in[6];
    const float* W2  = (const float*)d_in[7];
    const float* b2  = (const float*)d_in[8];
    float*       out = (float*)d_out;

    float *UT, *a1, *a2;
    void *hi, *lo, *hsh, *hsl, *w0h, *w0l;
    unsigned* sf;
    cudaGetSymbolAddress((void**)&UT, g_UT);
    cudaGetSymbolAddress((void**)&a1, g_a1);
    cudaGetSymbolAddress((void**)&a2, g_a2);
    cudaGetSymbolAddress(&hi, g_hi);
    cudaGetSymbolAddress(&lo, g_lo);
    cudaGetSymbolAddress(&hsh, g_hsh);
    cudaGetSymbolAddress(&hsl, g_hsl);
    cudaGetSymbolAddress(&w0h, g_w0h);
    cudaGetSymbolAddress(&w0l, g_w0l);
    cudaGetSymbolAddress((void**)&sf, g_sf);

    cudaFuncSetAttribute(scan_mma_kernel, cudaFuncAttributeMaxDynamicSharedMemorySize, SCAN_SMEM);
    cudaFuncSetAttribute(gemm_mma_kernel, cudaFuncAttributeMaxDynamicSharedMemorySize, GEMM_SMEM);

    u_kernel<<<dim3(16, 1024), 256>>>(x, Win, UT);
    wcvt_kernel<<<(HID_ * RES_ + 255) / 256, 256>>>(W0, (__nv_bfloat16*)w0h, (__nv_bfloat16*)w0l,
                                                    HID_ * RES_);
    cudaMemsetAsync(hi, 0, 2ull * B_ * RES_ * sizeof(__nv_bfloat16));
    cudaMemsetAsync(lo, 0, 2ull * B_ * RES_ * sizeof(__nv_bfloat16));
    cudaMemsetAsync(sf, 0, 1024 * sizeof(unsigned));

    scan_mma_kernel<<<NCTA_, 256, SCAN_SMEM>>>(Wh, UT);

    // grid axes swapped: x = n-tiles (8), y = m-tiles (256) -> same-A CTAs adjacent
    gemm_mma_kernel<<<dim3(HID_ / 64, BT_ / 128), 256, GEMM_SMEM>>>(
        (const __nv_bfloat16*)hsh, (const __nv_bfloat16*)hsl,
        (const __nv_bfloat16*)w0h, (const __nv_bfloat16*)w0l, b0, a1);
    gemm_kernel<1, 0><<<dim3(BT_ / 128, HID_ / 64), 256>>>(a1, HID_, W1, b1, a2, HID_);
    gemm_kernel<0, 1><<<dim3(BT_ / 128, 1), 256>>>(a2, HID_, W2, b2, out, OUT_);

    if (out_size >= (int)((size_t)B_ * T_ * OUT_ + (size_t)B_ * RES_))
        hn_kernel<<<RES_ * B_ / 256, 256>>>(UT + (size_t)(T_ - 1) * (RES_ * B_),
                                            out + (size_t)B_ * T_ * OUT_);
}